// round 1
// baseline (speedup 1.0000x reference)
#include <cuda_runtime.h>
#include <math.h>

#define BATCH 8
#define EE    16384

// ---------------- scratch (static __device__, no allocations) ----------------
__device__ float g_H1[33554432];          // [8][4096][1024] relu(MLP1)
__device__ float g_S[4194304];            // [8][512][1024]  masked-sum of H1
__device__ float g_pooled[6291456];       // [8][1024][768]
__device__ float g_hin[6297600];          // [8][1025][768]  row0 = text_vec
__device__ float g_h[2099200];            // [8][1025][256]
__device__ float g_q[2099200];
__device__ float g_k[2099200];
__device__ float g_v[2099200];
__device__ float g_tpv[25600];            // [100][256] type_table @ type_proj_w
__device__ float g_ET[25600];             // [2][50][256] edge_type_table @ gnn_we[l]
__device__ float g_Wc[64000];             // [1280][50] cls_w @ cls2_w^T
__device__ float g_bc[50];
__device__ float g_msum[8192];            // [8][1024]
__device__ int   g_cnt[8 * 1026];
__device__ int   g_off[8 * 1026];
__device__ int   g_cur[8 * 1026];
__device__ int   g_elist[131072];         // [8][16384]

// ---------------- text encoder: masked mean pool -> hin[b][0] ----------------
__global__ void text_kernel(const int* __restrict__ sentence,
                            const float* __restrict__ mask,
                            const float* __restrict__ we) {
    int b = blockIdx.x, t = threadIdx.x;
    __shared__ float sred[256];
    __shared__ float sm[256];
    __shared__ int   sidx[256];
    float mval = mask[b * 256 + t];
    sidx[t] = sentence[b * 256 + t];
    sm[t] = mval;
    sred[t] = mval;
    __syncthreads();
    for (int s = 128; s > 0; s >>= 1) { if (t < s) sred[t] += sred[t + s]; __syncthreads(); }
    float denom = sred[0] + 1e-9f;
    float a0 = 0.f, a1 = 0.f, a2 = 0.f;
    for (int l = 0; l < 256; l++) {
        const float* row = we + (long long)sidx[l] * 768;
        float m = sm[l];
        a0 += row[t] * m; a1 += row[256 + t] * m; a2 += row[512 + t] * m;
    }
    float* o = g_hin + (long long)b * 1025 * 768;
    o[t] = a0 / denom; o[256 + t] = a1 / denom; o[512 + t] = a2 / denom;
}

// ---------------- small matmuls (precomputes) ----------------
__global__ void smallmm(const float* __restrict__ A, const float* __restrict__ Bm,
                        float* __restrict__ Cm, int Mv, int Nv, int Kv, int transB) {
    int i = blockIdx.x * blockDim.x + threadIdx.x;
    if (i >= Mv * Nv) return;
    int r = i / Nv, c = i % Nv;
    float s = 0.f;
    if (transB) { for (int k = 0; k < Kv; k++) s += A[r * Kv + k] * Bm[c * Kv + k]; }
    else        { for (int k = 0; k < Kv; k++) s += A[r * Kv + k] * Bm[k * Nv + c]; }
    Cm[i] = s;
}

__global__ void bc_kernel(const float* __restrict__ cls_b,
                          const float* __restrict__ cls2_w,
                          const float* __restrict__ cls2_b) {
    int c = threadIdx.x;
    if (c >= 50) return;
    float s = cls2_b[c];
    for (int j = 0; j < 768; j++) s += cls_b[j] * cls2_w[c * 768 + j];
    g_bc[c] = s;
}

// ---------------- node-mask sums and kg pooling ----------------
__global__ void msum_kernel(const float* __restrict__ nm) {
    int b = blockIdx.x, n = threadIdx.x;
    const float* m = nm + ((long long)b * 1024 + n) * 8;
    float s = 0.f;
    #pragma unroll
    for (int i = 0; i < 8; i++) s += m[i];
    g_msum[b * 1024 + n] = s;
}

__global__ void poolkg_kernel(const int* __restrict__ nodes,
                              const float* __restrict__ nm,
                              const float* __restrict__ etab) {
    int n = blockIdx.x, b = blockIdx.y, t = threadIdx.x;
    const int* idx = nodes + ((long long)b * 1024 + n) * 8;
    const float* m = nm + ((long long)b * 1024 + n) * 8;
    long long base[8]; float mv[8];
    #pragma unroll
    for (int i = 0; i < 8; i++) { base[i] = (long long)idx[i] * 768; mv[i] = m[i]; }
    float* o = g_pooled + ((long long)b * 1024 + n) * 768;
    for (int e = t; e < 768; e += 256) {
        float s = 0.f;
        #pragma unroll
        for (int i = 0; i < 8; i++) s += etab[base[i] + e] * mv[i];
        o[e] = s;
    }
}

__global__ void reduceS_kernel(const float* __restrict__ nm) {
    int n = blockIdx.x, b = blockIdx.y, t = threadIdx.x;
    const float* h1 = g_H1 + ((long long)b * 4096 + n * 8) * 1024;
    const float* m = nm + ((long long)b * 1024 + 512 + n) * 8;
    float ml[8];
    #pragma unroll
    for (int i = 0; i < 8; i++) ml[i] = m[i];
    float* o = g_S + ((long long)b * 512 + n) * 1024;
    for (int j = t; j < 1024; j += 256) {
        float s = 0.f;
        #pragma unroll
        for (int i = 0; i < 8; i++) s += h1[(long long)i * 1024 + j] * ml[i];
        o[j] = s;
    }
}

// ---------------- batched SGEMM 128x128x8, optional A-row gather ----------------
__global__ __launch_bounds__(256, 2) void gemm128(
    const float* __restrict__ A, long long sA,
    const float* __restrict__ gtab, const int* __restrict__ gidx, long long sG,
    const float* __restrict__ W,
    float* __restrict__ Cp, long long sC,
    int Mr, int Nc, int Kd,
    const float* __restrict__ bias,
    const float* __restrict__ rowScale, long long sRS,
    const float* __restrict__ addTab, const int* __restrict__ aidx, long long sAI,
    int relu)
{
    __shared__ float As[8][128];
    __shared__ float Bs[8][128];
    const int b = blockIdx.z;
    const int mBase = blockIdx.y * 128;
    const int nBase = blockIdx.x * 128;
    const int tid = threadIdx.x;
    const int laRow = tid >> 1;
    const int laK = (tid & 1) * 4;
    const int lbK = tid >> 5;
    const int lbC = (tid & 31) * 4;
    const int ty = tid >> 4;
    const int tx = tid & 15;

    float acc[8][8];
    #pragma unroll
    for (int i = 0; i < 8; i++)
        #pragma unroll
        for (int j = 0; j < 8; j++) acc[i][j] = 0.f;

    const int arow = mBase + laRow;
    const bool aval = arow < Mr;
    const float* aptr;
    if (gidx) {
        aptr = aval ? (gtab + (long long)gidx[b * sG + arow] * Kd) : gtab;
    } else {
        aptr = A + b * sA + (long long)arow * Kd;
    }
    const float* wbase = W + nBase + lbC;

    for (int k0 = 0; k0 < Kd; k0 += 8) {
        float4 av = make_float4(0.f, 0.f, 0.f, 0.f);
        if (aval) av = *reinterpret_cast<const float4*>(aptr + k0 + laK);
        float4 bv = *reinterpret_cast<const float4*>(wbase + (long long)(k0 + lbK) * Nc);
        __syncthreads();
        As[laK + 0][laRow] = av.x;
        As[laK + 1][laRow] = av.y;
        As[laK + 2][laRow] = av.z;
        As[laK + 3][laRow] = av.w;
        *reinterpret_cast<float4*>(&Bs[lbK][lbC]) = bv;
        __syncthreads();
        #pragma unroll
        for (int kk = 0; kk < 8; kk++) {
            float a8[8], b8[8];
            *reinterpret_cast<float4*>(&a8[0]) = *reinterpret_cast<const float4*>(&As[kk][ty * 8]);
            *reinterpret_cast<float4*>(&a8[4]) = *reinterpret_cast<const float4*>(&As[kk][ty * 8 + 4]);
            *reinterpret_cast<float4*>(&b8[0]) = *reinterpret_cast<const float4*>(&Bs[kk][tx * 8]);
            *reinterpret_cast<float4*>(&b8[4]) = *reinterpret_cast<const float4*>(&Bs[kk][tx * 8 + 4]);
            #pragma unroll
            for (int i = 0; i < 8; i++)
                #pragma unroll
                for (int j = 0; j < 8; j++) acc[i][j] = fmaf(a8[i], b8[j], acc[i][j]);
        }
    }

    #pragma unroll
    for (int i = 0; i < 8; i++) {
        int row = mBase + ty * 8 + i;
        if (row >= Mr) continue;
        float rs = rowScale ? rowScale[b * sRS + row] : 1.f;
        const float* addrow = addTab ? (addTab + (long long)aidx[b * sAI + row] * Nc) : nullptr;
        float* crow = Cp + b * sC + (long long)row * Nc;
        #pragma unroll
        for (int j = 0; j < 8; j++) {
            int col = nBase + tx * 8 + j;
            float vv = acc[i][j];
            if (bias) vv += bias[col] * rs;
            if (addrow) vv += addrow[col];
            if (relu) vv = fmaxf(vv, 0.f);
            crow[col] = vv;
        }
    }
}

// ---------------- CSR build ----------------
__global__ void zero_cnt() {
    int i = blockIdx.x * blockDim.x + threadIdx.x;
    if (i < 8 * 1026) g_cnt[i] = 0;
}
__global__ void count_kernel(const int* __restrict__ edges) {
    int i = blockIdx.x * blockDim.x + threadIdx.x;
    if (i >= BATCH * EE) return;
    int b = i / EE, e = i % EE;
    int dst = edges[(long long)b * 2 * EE + EE + e];
    atomicAdd(&g_cnt[b * 1026 + dst], 1);
}
__global__ void scan_kernel() {
    int b = threadIdx.x;
    if (b >= 8) return;
    int acc = 0;
    for (int i = 0; i < 1026; i++) {
        g_off[b * 1026 + i] = acc;
        g_cur[b * 1026 + i] = acc;
        if (i < 1025) acc += g_cnt[b * 1026 + i];
    }
}
__global__ void fill_kernel(const int* __restrict__ edges) {
    int i = blockIdx.x * blockDim.x + threadIdx.x;
    if (i >= BATCH * EE) return;
    int b = i / EE, e = i % EE;
    int dst = edges[(long long)b * 2 * EE + EE + e];
    int pos = atomicAdd(&g_cur[b * 1026 + dst], 1);
    g_elist[b * EE + pos] = e;
}

// ---------------- fused GNN attention layer (per dst node) ----------------
__device__ __forceinline__ unsigned fenc(float f) {
    unsigned u = __float_as_uint(f);
    return (u & 0x80000000u) ? ~u : (u | 0x80000000u);
}
__device__ __forceinline__ float fdec(unsigned e) {
    return (e & 0x80000000u) ? __uint_as_float(e ^ 0x80000000u) : __uint_as_float(~e);
}

__global__ __launch_bounds__(256) void gnn_edge_kernel(
    const float* __restrict__ q, const float* __restrict__ k, const float* __restrict__ v,
    float* __restrict__ h,
    const int* __restrict__ edges, const int* __restrict__ etyp,
    const float* __restrict__ ET)
{
    const int node = blockIdx.x;
    const int b = blockIdx.y;
    const int tid = threadIdx.x;
    const int lane = tid & 31;
    const int w = tid >> 5;
    __shared__ float qs[256];
    __shared__ unsigned smax[4];
    __shared__ float sden[4];
    __shared__ float sagg[256];
    const long long rowOff = ((long long)b * 1025 + node) * 256;
    qs[tid] = q[rowOff + tid];
    sagg[tid] = 0.f;
    if (tid < 4) { smax[tid] = 0u; sden[tid] = 0.f; }
    __syncthreads();
    const int off = g_off[b * 1026 + node];
    const int deg = g_off[b * 1026 + node + 1] - off;
    const int* el = g_elist + b * EE + off;
    const int* srcArr = edges + (long long)b * 2 * EE;

    float lmax[4] = { -1e30f, -1e30f, -1e30f, -1e30f };
    for (int ei = w; ei < deg; ei += 8) {
        int e = el[ei];
        int src = srcArr[e];
        int et = etyp[(long long)b * EE + e];
        const float* kr = k + ((long long)b * 1025 + src) * 256;
        const float* er = ET + et * 256;
        float hc[4] = {0.f, 0.f, 0.f, 0.f};
        #pragma unroll
        for (int i = 0; i < 8; i++) {
            int d = i * 32 + lane;
            hc[i >> 1] += qs[d] * (kr[d] + er[d]);
        }
        #pragma unroll
        for (int s = 16; s > 0; s >>= 1) {
            #pragma unroll
            for (int hh = 0; hh < 4; hh++) hc[hh] += __shfl_xor_sync(0xffffffffu, hc[hh], s);
        }
        #pragma unroll
        for (int hh = 0; hh < 4; hh++) lmax[hh] = fmaxf(lmax[hh], hc[hh] * 0.125f);
    }
    if (lane == 0 && deg > 0) {
        #pragma unroll
        for (int hh = 0; hh < 4; hh++) atomicMax(&smax[hh], fenc(lmax[hh]));
    }
    __syncthreads();
    float mx[4];
    #pragma unroll
    for (int hh = 0; hh < 4; hh++) mx[hh] = fdec(smax[hh]);

    float vacc[8] = {0.f, 0.f, 0.f, 0.f, 0.f, 0.f, 0.f, 0.f};
    float wsum[4] = {0.f, 0.f, 0.f, 0.f};
    for (int ei = w; ei < deg; ei += 8) {
        int e = el[ei];
        int src = srcArr[e];
        int et = etyp[(long long)b * EE + e];
        const float* kr = k + ((long long)b * 1025 + src) * 256;
        const float* er = ET + et * 256;
        float hc[4] = {0.f, 0.f, 0.f, 0.f};
        #pragma unroll
        for (int i = 0; i < 8; i++) {
            int d = i * 32 + lane;
            hc[i >> 1] += qs[d] * (kr[d] + er[d]);
        }
        #pragma unroll
        for (int s = 16; s > 0; s >>= 1) {
            #pragma unroll
            for (int hh = 0; hh < 4; hh++) hc[hh] += __shfl_xor_sync(0xffffffffu, hc[hh], s);
        }
        float ex[4];
        #pragma unroll
        for (int hh = 0; hh < 4; hh++) ex[hh] = expf(hc[hh] * 0.125f - mx[hh]);
        const float* vr = v + ((long long)b * 1025 + src) * 256;
        #pragma unroll
        for (int i = 0; i < 8; i++) {
            int d = i * 32 + lane;
            vacc[i] += ex[i >> 1] * vr[d];
        }
        if (lane == 0) {
            #pragma unroll
            for (int hh = 0; hh < 4; hh++) wsum[hh] += ex[hh];
        }
    }
    if (lane == 0 && deg > 0) {
        #pragma unroll
        for (int hh = 0; hh < 4; hh++) atomicAdd(&sden[hh], wsum[hh]);
    }
    #pragma unroll
    for (int i = 0; i < 8; i++) atomicAdd(&sagg[i * 32 + lane], vacc[i]);
    __syncthreads();
    float den = sden[tid >> 6] + 1e-9f;
    float val = h[rowOff + tid] + sagg[tid] / den;
    h[rowOff + tid] = fmaxf(val, 0.f);
}

// ---------------- final classifier ----------------
__global__ void out_kernel(float* __restrict__ out) {
    int c = blockIdx.x, b = blockIdx.y, t = threadIdx.x;
    __shared__ float red[256];
    const float* ctx = g_h + (long long)b * 1025 * 256;
    const float* lab = g_h + ((long long)b * 1025 + 1 + c) * 256;
    const float* txt = g_hin + (long long)b * 1025 * 768;
    float s = 0.f;
    for (int kx = t; kx < 1280; kx += 256) {
        float x;
        if (kx < 256) x = ctx[kx];
        else if (kx < 512) x = lab[kx - 256];
        else x = txt[kx - 512];
        s += x * g_Wc[kx * 50 + c];
    }
    red[t] = s;
    __syncthreads();
    for (int st = 128; st > 0; st >>= 1) { if (t < st) red[t] += red[t + st]; __syncthreads(); }
    if (t == 0) out[b * 50 + c] = red[0] + g_bc[c];
}

// ---------------- host ----------------
static void launch_gemm(const float* A, long long sA,
                        const float* gtab, const int* gidx, long long sG,
                        const float* W, float* Cp, long long sC,
                        int Mr, int Nc, int Kd,
                        const float* bias, const float* rowScale, long long sRS,
                        const float* addTab, const int* aidx, long long sAI, int relu) {
    dim3 grid(Nc / 128, (Mr + 127) / 128, BATCH);
    gemm128<<<grid, 256>>>(A, sA, gtab, gidx, sG, W, Cp, sC, Mr, Nc, Kd,
                           bias, rowScale, sRS, addTab, aidx, sAI, relu);
}

extern "C" void kernel_launch(void* const* d_in, const int* in_sizes, int n_in,
                              void* d_out, int out_size) {
    (void)in_sizes; (void)n_in; (void)out_size;
    const int*   sentence        = (const int*)d_in[0];
    const float* mask            = (const float*)d_in[1];
    const int*   nodes           = (const int*)d_in[2];
    const float* node_mask       = (const float*)d_in[3];
    const int*   node_types      = (const int*)d_in[4];
    const int*   edges           = (const int*)d_in[5];
    const int*   edge_types      = (const int*)d_in[6];
    const float* word_embed      = (const float*)d_in[7];
    const float* entity_table    = (const float*)d_in[8];
    const float* type_table      = (const float*)d_in[9];
    const float* mlp_w1          = (const float*)d_in[10];
    const float* mlp_b1          = (const float*)d_in[11];
    const float* mlp_w2          = (const float*)d_in[12];
    const float* mlp_b2          = (const float*)d_in[13];
    const float* ntw_w           = (const float*)d_in[14];
    const float* proj_w          = (const float*)d_in[15];
    const float* proj_b          = (const float*)d_in[16];
    const float* type_proj_w     = (const float*)d_in[17];
    const float* edge_type_table = (const float*)d_in[18];
    const float* gnn_wq          = (const float*)d_in[19];
    const float* gnn_wk          = (const float*)d_in[20];
    const float* gnn_wv          = (const float*)d_in[21];
    const float* gnn_we          = (const float*)d_in[22];
    const float* cls_w           = (const float*)d_in[23];
    const float* cls_b           = (const float*)d_in[24];
    const float* cls2_w          = (const float*)d_in[25];
    const float* cls2_b          = (const float*)d_in[26];
    float* out = (float*)d_out;

    float *pH1, *pS, *pPool, *pHin, *pH, *pQ, *pK, *pV, *pTpv, *pET, *pWc, *pMsum;
    cudaGetSymbolAddress((void**)&pH1, g_H1);
    cudaGetSymbolAddress((void**)&pS, g_S);
    cudaGetSymbolAddress((void**)&pPool, g_pooled);
    cudaGetSymbolAddress((void**)&pHin, g_hin);
    cudaGetSymbolAddress((void**)&pH, g_h);
    cudaGetSymbolAddress((void**)&pQ, g_q);
    cudaGetSymbolAddress((void**)&pK, g_k);
    cudaGetSymbolAddress((void**)&pV, g_v);
    cudaGetSymbolAddress((void**)&pTpv, g_tpv);
    cudaGetSymbolAddress((void**)&pET, g_ET);
    cudaGetSymbolAddress((void**)&pWc, g_Wc);
    cudaGetSymbolAddress((void**)&pMsum, g_msum);

    // text vector -> hin[b][0]
    text_kernel<<<8, 256>>>(sentence, mask, word_embed);
    // precomputes
    smallmm<<<(100 * 256 + 255) / 256, 256>>>(type_table, type_proj_w, pTpv, 100, 256, 50, 0);
    smallmm<<<(50 * 256 + 255) / 256, 256>>>(edge_type_table, gnn_we, pET, 50, 256, 50, 0);
    smallmm<<<(50 * 256 + 255) / 256, 256>>>(edge_type_table, gnn_we + 50 * 256, pET + 50 * 256, 50, 256, 50, 0);
    smallmm<<<(1280 * 50 + 255) / 256, 256>>>(cls_w, cls2_w, pWc, 1280, 50, 768, 1);
    bc_kernel<<<1, 64>>>(cls_b, cls2_w, cls2_b);
    msum_kernel<<<8, 1024>>>(node_mask);
    // kg-half pooling (linear, commuted past ntw)
    poolkg_kernel<<<dim3(512, 8), 256>>>(nodes, node_mask, entity_table);
    // MLP1 with gathered A rows: relu(E[idx] @ W1 + b1) -> H1
    launch_gemm(nullptr, 0, entity_table, nodes + 4096, 8192,
                mlp_w1, pH1, 4096LL * 1024, 4096, 1024, 768,
                mlp_b1, nullptr, 0, nullptr, nullptr, 0, 1);
    // masked sum over M -> S
    reduceS_kernel<<<dim3(512, 8), 256>>>(node_mask);
    // MLP2 commuted: S @ W2 + b2*msum -> pooled[512:]
    launch_gemm(pS, 512LL * 1024, nullptr, nullptr, 0,
                mlp_w2, pPool + 512 * 768, 1024LL * 768, 512, 768, 1024,
                mlp_b2, pMsum + 512, 1024, nullptr, nullptr, 0, 0);
    // ntw: pooled @ ntw_w -> hin[b][1:]
    launch_gemm(pPool, 1024LL * 768, nullptr, nullptr, 0,
                ntw_w, pHin + 768, 1025LL * 768, 1024, 768, 768,
                nullptr, nullptr, 0, nullptr, nullptr, 0, 0);
    // proj: hin @ proj_w + proj_b + tpv[node_types] -> h
    launch_gemm(pHin, 1025LL * 768, nullptr, nullptr, 0,
                proj_w, pH, 1025LL * 256, 1025, 256, 768,
                proj_b, nullptr, 0, pTpv, node_types, 1025, 0);
    // CSR of edges by dst
    zero_cnt<<<(8 * 1026 + 255) / 256, 256>>>();
    count_kernel<<<(BATCH * EE) / 256, 256>>>(edges);
    scan_kernel<<<1, 8>>>();
    fill_kernel<<<(BATCH * EE) / 256, 256>>>(edges);
    // GNN layers
    for (int l = 0; l < 2; l++) {
        launch_gemm(pH, 1025LL * 256, nullptr, nullptr, 0,
                    gnn_wq + l * 65536, pQ, 1025LL * 256, 1025, 256, 256,
                    nullptr, nullptr, 0, nullptr, nullptr, 0, 0);
        launch_gemm(pH, 1025LL * 256, nullptr, nullptr, 0,
                    gnn_wk + l * 65536, pK, 1025LL * 256, 1025, 256, 256,
                    nullptr, nullptr, 0, nullptr, nullptr, 0, 0);
        launch_gemm(pH, 1025LL * 256, nullptr, nullptr, 0,
                    gnn_wv + l * 65536, pV, 1025LL * 256, 1025, 256, 256,
                    nullptr, nullptr, 0, nullptr, nullptr, 0, 0);
        gnn_edge_kernel<<<dim3(1025, 8), 256>>>(pQ, pK, pV, pH, edges, edge_types,
                                                pET + l * 50 * 256);
    }
    // fused classifier
    out_kernel<<<dim3(50, 8), 256>>>(out);
}

// round 4
// speedup vs baseline: 1.7094x; 1.7094x over previous
#include <cuda_runtime.h>
#include <cuda_bf16.h>
#include <cstdint>
#include <math.h>

#define BATCH 8
#define EE    16384

// ============================ scratch ============================
__device__ float g_H1[33554432];          // [8][4096][1024] relu(MLP1)
__device__ float g_S[4194304];            // [8][512][1024]
__device__ float g_pooled[6291456];       // [8][1024][768]
__device__ float g_hin[6297600];          // [8][1025][768]
__device__ float g_h[2099200];            // [8][1025][256]
__device__ float g_q[2099200];
__device__ float g_k[2099200];
__device__ float g_v[2099200];
__device__ float g_tpv[25600];
__device__ float g_ET[25600];
__device__ float g_Wc[64000];
__device__ float g_bc[50];
__device__ float g_msum[8192];
__device__ int   g_cnt[8 * 1026];
__device__ int   g_off[8 * 1026];
__device__ int   g_cur[8 * 1026];
__device__ int   g_elist[131072];
// bf16 split weight tables, transposed to [N][K]
__device__ __nv_bfloat16 g_WH[2752512];
__device__ __nv_bfloat16 g_WL[2752512];
#define OFF_W1   0
#define OFF_W2   786432
#define OFF_NTW  1572864
#define OFF_PROJ 2162688
#define OFF_QKV  2359296

// ============================ helpers ============================
__device__ __forceinline__ uint32_t smem_u32(const void* p) {
    uint32_t a;
    asm("{ .reg .u64 t; cvta.to.shared.u64 t, %1; cvt.u32.u64 %0, t; }" : "=r"(a) : "l"(p));
    return a;
}
__device__ __forceinline__ void ldsm_x4(uint32_t (&r)[4], uint32_t addr) {
    asm volatile("ldmatrix.sync.aligned.m8n8.x4.shared.b16 {%0,%1,%2,%3}, [%4];"
                 : "=r"(r[0]), "=r"(r[1]), "=r"(r[2]), "=r"(r[3]) : "r"(addr));
}
__device__ __forceinline__ void mma16816(float* c, const uint32_t* a, uint32_t b0, uint32_t b1) {
    asm volatile("mma.sync.aligned.m16n8k16.row.col.f32.bf16.bf16.f32 "
                 "{%0,%1,%2,%3}, {%4,%5,%6,%7}, {%8,%9}, {%0,%1,%2,%3};"
                 : "+f"(c[0]), "+f"(c[1]), "+f"(c[2]), "+f"(c[3])
                 : "r"(a[0]), "r"(a[1]), "r"(a[2]), "r"(a[3]), "r"(b0), "r"(b1));
}

// ============================ text encoder ============================
__global__ void text_kernel(const int* __restrict__ sentence,
                            const float* __restrict__ mask,
                            const float* __restrict__ we) {
    int b = blockIdx.x, t = threadIdx.x;
    __shared__ float sred[256];
    __shared__ float sm[256];
    __shared__ int   sidx[256];
    float mval = mask[b * 256 + t];
    sidx[t] = sentence[b * 256 + t];
    sm[t] = mval;
    sred[t] = mval;
    __syncthreads();
    for (int s = 128; s > 0; s >>= 1) { if (t < s) sred[t] += sred[t + s]; __syncthreads(); }
    float denom = sred[0] + 1e-9f;
    float a0 = 0.f, a1 = 0.f, a2 = 0.f;
    for (int l = 0; l < 256; l++) {
        const float* row = we + (long long)sidx[l] * 768;
        float m = sm[l];
        a0 += row[t] * m; a1 += row[256 + t] * m; a2 += row[512 + t] * m;
    }
    float* o = g_hin + (long long)b * 1025 * 768;
    o[t] = a0 / denom; o[256 + t] = a1 / denom; o[512 + t] = a2 / denom;
}

// ============================ small precomputes ============================
__global__ void smallmm(const float* __restrict__ A, const float* __restrict__ Bm,
                        float* __restrict__ Cm, int Mv, int Nv, int Kv, int transB) {
    int i = blockIdx.x * blockDim.x + threadIdx.x;
    if (i >= Mv * Nv) return;
    int r = i / Nv, c = i % Nv;
    float s = 0.f;
    if (transB) { for (int k = 0; k < Kv; k++) s += A[r * Kv + k] * Bm[c * Kv + k]; }
    else        { for (int k = 0; k < Kv; k++) s += A[r * Kv + k] * Bm[k * Nv + c]; }
    Cm[i] = s;
}

__global__ void bc_kernel(const float* __restrict__ cls_b,
                          const float* __restrict__ cls2_w,
                          const float* __restrict__ cls2_b) {
    int c = threadIdx.x;
    if (c >= 50) return;
    float s = cls2_b[c];
    for (int j = 0; j < 768; j++) s += cls_b[j] * cls2_w[c * 768 + j];
    g_bc[c] = s;
}

// transpose + bf16 hi/lo split: W[K,N] fp32 -> out[N,K] bf16
__global__ void prep_w(const float* __restrict__ W, __nv_bfloat16* __restrict__ oh,
                       __nv_bfloat16* __restrict__ ol, int K, int N) {
    int idx = blockIdx.x * blockDim.x + threadIdx.x;
    if (idx >= K * N) return;
    int n = idx / K, k = idx % K;
    float a = W[(long long)k * N + n];
    __nv_bfloat16 h = __float2bfloat16(a);
    oh[idx] = h;
    ol[idx] = __float2bfloat16(a - __bfloat162float(h));
}

// ============================ pooling kernels ============================
__global__ void msum_kernel(const float* __restrict__ nm) {
    int b = blockIdx.x, n = threadIdx.x;
    const float* m = nm + ((long long)b * 1024 + n) * 8;
    float s = 0.f;
    #pragma unroll
    for (int i = 0; i < 8; i++) s += m[i];
    g_msum[b * 1024 + n] = s;
}

__global__ void poolkg_kernel(const int* __restrict__ nodes,
                              const float* __restrict__ nm,
                              const float* __restrict__ etab) {
    int n = blockIdx.x, b = blockIdx.y, t = threadIdx.x;
    const int* idx = nodes + ((long long)b * 1024 + n) * 8;
    const float* m = nm + ((long long)b * 1024 + n) * 8;
    long long base[8]; float mv[8];
    #pragma unroll
    for (int i = 0; i < 8; i++) { base[i] = (long long)idx[i] * 768; mv[i] = m[i]; }
    float* o = g_pooled + ((long long)b * 1024 + n) * 768;
    for (int e = t; e < 768; e += 256) {
        float s = 0.f;
        #pragma unroll
        for (int i = 0; i < 8; i++) s += etab[base[i] + e] * mv[i];
        o[e] = s;
    }
}

__global__ void reduceS_kernel(const float* __restrict__ nm) {
    int n = blockIdx.x, b = blockIdx.y, t = threadIdx.x;
    const float* h1 = g_H1 + ((long long)b * 4096 + n * 8) * 1024;
    const float* m = nm + ((long long)b * 1024 + 512 + n) * 8;
    float ml[8];
    #pragma unroll
    for (int i = 0; i < 8; i++) ml[i] = m[i];
    float* o = g_S + ((long long)b * 512 + n) * 1024;
    for (int j = t; j < 1024; j += 256) {
        float s = 0.f;
        #pragma unroll
        for (int i = 0; i < 8; i++) s += h1[(long long)i * 1024 + j] * ml[i];
        o[j] = s;
    }
}

// ============================ split-bf16 HMMA GEMM ============================
// C[b] = A[b] @ W. W pre-transposed + split into Bh/Bl [Nc][Kd] bf16.
// CTA tile 128x128, ktile 32, 8 warps (warp tile 32x64), mma.sync m16n8k16.
#define LDK 40   // padded k stride (elements) for smem tiles

__global__ __launch_bounds__(256) void gemm_mma(
    const float* __restrict__ A, long long sA,
    const float* __restrict__ gtab, const int* __restrict__ gidx, long long sG,
    const __nv_bfloat16* __restrict__ Bh, const __nv_bfloat16* __restrict__ Bl,
    float* __restrict__ C, long long sC,
    int Mr, int Nc, int Kd,
    const float* __restrict__ bias,
    const float* __restrict__ rowScale, long long sRS,
    const float* __restrict__ addTab, const int* __restrict__ aidx, long long sAI,
    int relu)
{
    __shared__ __nv_bfloat16 sAh[128 * LDK];
    __shared__ __nv_bfloat16 sAl[128 * LDK];
    __shared__ __nv_bfloat16 sBh[128 * LDK];
    __shared__ __nv_bfloat16 sBl[128 * LDK];

    const int tid = threadIdx.x;
    const int lane = tid & 31;
    const int wid = tid >> 5;
    const int b = blockIdx.z;
    const int nBase = blockIdx.x * 128;
    const int mBase = blockIdx.y * 128;

    // ---- loader role: thread t covers (row = t>>1, khalf = (t&1)*16) ----
    const int lrow = tid >> 1;
    const int lkh = (tid & 1) * 16;
    const int arow = mBase + lrow;
    const bool aval = arow < Mr;
    const float* aptr;
    if (gidx) aptr = gtab + (long long)(aval ? gidx[b * sG + arow] : 0) * Kd + lkh;
    else      aptr = A + b * sA + (long long)arow * Kd + lkh;
    const __nv_bfloat16* bhp = Bh + (long long)(nBase + lrow) * Kd + lkh;
    const __nv_bfloat16* blp = Bl + (long long)(nBase + lrow) * Kd + lkh;

    const uint32_t uAh = smem_u32(sAh), uAl = smem_u32(sAl);
    const uint32_t uBh = smem_u32(sBh), uBl = smem_u32(sBl);
    const uint32_t stsOff = (uint32_t)(lrow * LDK + lkh) * 2;

    // ---- mma role ----
    const int wm = (wid & 3) * 32;
    const int wn = (wid >> 2) * 64;
    float acc[2][8][4];
    #pragma unroll
    for (int mt = 0; mt < 2; mt++)
        #pragma unroll
        for (int nt = 0; nt < 8; nt++)
            #pragma unroll
            for (int q = 0; q < 4; q++) acc[mt][nt][q] = 0.f;

    // ldmatrix addresses (element offsets; ks added per step)
    const uint32_t aRowOff = (uint32_t)((wm + (lane & 15)) * LDK + (lane >> 4) * 8) * 2;
    const uint32_t bRowOff = (uint32_t)((wn + (lane & 7) + (lane >> 4) * 8) * LDK + ((lane >> 3) & 1) * 8) * 2;

    float4 stA[4];
    uint4  stBh[2], stBl[2];

    // prefetch ktile 0
    {
        if (aval) {
            stA[0] = *reinterpret_cast<const float4*>(aptr + 0);
            stA[1] = *reinterpret_cast<const float4*>(aptr + 4);
            stA[2] = *reinterpret_cast<const float4*>(aptr + 8);
            stA[3] = *reinterpret_cast<const float4*>(aptr + 12);
        } else {
            stA[0] = stA[1] = stA[2] = stA[3] = make_float4(0.f, 0.f, 0.f, 0.f);
        }
        stBh[0] = *reinterpret_cast<const uint4*>(bhp);
        stBh[1] = *reinterpret_cast<const uint4*>(bhp + 8);
        stBl[0] = *reinterpret_cast<const uint4*>(blp);
        stBl[1] = *reinterpret_cast<const uint4*>(blp + 8);
    }

    const int nkt = Kd >> 5;
    for (int kt = 0; kt < nkt; kt++) {
        // ---- STS staged tile ----
        {
            __nv_bfloat16 hh[16], ll[16];
            const float* af = reinterpret_cast<const float*>(stA);
            #pragma unroll
            for (int i = 0; i < 16; i++) {
                float x = af[i];
                __nv_bfloat16 h = __float2bfloat16(x);
                hh[i] = h;
                ll[i] = __float2bfloat16(x - __bfloat162float(h));
            }
            *reinterpret_cast<uint4*>(reinterpret_cast<char*>(sAh) + stsOff) = *reinterpret_cast<uint4*>(&hh[0]);
            *reinterpret_cast<uint4*>(reinterpret_cast<char*>(sAh) + stsOff + 16) = *reinterpret_cast<uint4*>(&hh[8]);
            *reinterpret_cast<uint4*>(reinterpret_cast<char*>(sAl) + stsOff) = *reinterpret_cast<uint4*>(&ll[0]);
            *reinterpret_cast<uint4*>(reinterpret_cast<char*>(sAl) + stsOff + 16) = *reinterpret_cast<uint4*>(&ll[8]);
            *reinterpret_cast<uint4*>(reinterpret_cast<char*>(sBh) + stsOff) = stBh[0];
            *reinterpret_cast<uint4*>(reinterpret_cast<char*>(sBh) + stsOff + 16) = stBh[1];
            *reinterpret_cast<uint4*>(reinterpret_cast<char*>(sBl) + stsOff) = stBl[0];
            *reinterpret_cast<uint4*>(reinterpret_cast<char*>(sBl) + stsOff + 16) = stBl[1];
        }
        __syncthreads();

        // ---- prefetch next ktile (overlaps with mma below) ----
        if (kt + 1 < nkt) {
            const int k0 = (kt + 1) * 32;
            if (aval) {
                stA[0] = *reinterpret_cast<const float4*>(aptr + k0 + 0);
                stA[1] = *reinterpret_cast<const float4*>(aptr + k0 + 4);
                stA[2] = *reinterpret_cast<const float4*>(aptr + k0 + 8);
                stA[3] = *reinterpret_cast<const float4*>(aptr + k0 + 12);
            }
            stBh[0] = *reinterpret_cast<const uint4*>(bhp + k0);
            stBh[1] = *reinterpret_cast<const uint4*>(bhp + k0 + 8);
            stBl[0] = *reinterpret_cast<const uint4*>(blp + k0);
            stBl[1] = *reinterpret_cast<const uint4*>(blp + k0 + 8);
        }

        // ---- compute ktile ----
        #pragma unroll
        for (int ks = 0; ks < 2; ks++) {
            const uint32_t kso = (uint32_t)(ks * 16) * 2;
            uint32_t ah[2][4], al[2][4];
            #pragma unroll
            for (int mt = 0; mt < 2; mt++) {
                uint32_t ao = aRowOff + (uint32_t)(mt * 16 * LDK) * 2 + kso;
                ldsm_x4(ah[mt], uAh + ao);
                ldsm_x4(al[mt], uAl + ao);
            }
            #pragma unroll
            for (int nt4 = 0; nt4 < 4; nt4++) {
                uint32_t bo = bRowOff + (uint32_t)(nt4 * 16 * LDK) * 2 + kso;
                uint32_t bh[4], bl[4];
                ldsm_x4(bh, uBh + bo);
                ldsm_x4(bl, uBl + bo);
                #pragma unroll
                for (int mt = 0; mt < 2; mt++) {
                    #pragma unroll
                    for (int hf = 0; hf < 2; hf++) {
                        float* c = acc[mt][nt4 * 2 + hf];
                        mma16816(c, ah[mt], bh[hf * 2], bh[hf * 2 + 1]);
                        mma16816(c, ah[mt], bl[hf * 2], bl[hf * 2 + 1]);
                        mma16816(c, al[mt], bh[hf * 2], bh[hf * 2 + 1]);
                    }
                }
            }
        }
        __syncthreads();
    }

    // ---- epilogue from accum registers ----
    #pragma unroll
    for (int mt = 0; mt < 2; mt++) {
        const int rbase = mBase + wm + mt * 16 + (lane >> 2);
        #pragma unroll
        for (int ri = 0; ri < 2; ri++) {
            const int row = rbase + ri * 8;
            if (row >= Mr) continue;
            float rs = 1.f;
            if (rowScale) rs = rowScale[b * sRS + row];
            const float* addrow = nullptr;
            if (addTab) addrow = addTab + (long long)aidx[b * sAI + row] * Nc;
            float* crow = C + b * sC + (long long)row * Nc;
            #pragma unroll
            for (int nt = 0; nt < 8; nt++) {
                const int col = nBase + wn + nt * 8 + (lane & 3) * 2;
                float v0 = acc[mt][nt][ri * 2 + 0];
                float v1 = acc[mt][nt][ri * 2 + 1];
                if (bias) { v0 += bias[col] * rs; v1 += bias[col + 1] * rs; }
                if (addrow) { v0 += addrow[col]; v1 += addrow[col + 1]; }
                if (relu) { v0 = fmaxf(v0, 0.f); v1 = fmaxf(v1, 0.f); }
                *reinterpret_cast<float2*>(crow + col) = make_float2(v0, v1);
            }
        }
    }
}

// ============================ CSR build ============================
__global__ void zero_cnt() {
    int i = blockIdx.x * blockDim.x + threadIdx.x;
    if (i < 8 * 1026) g_cnt[i] = 0;
}
__global__ void count_kernel(const int* __restrict__ edges) {
    int i = blockIdx.x * blockDim.x + threadIdx.x;
    if (i >= BATCH * EE) return;
    int b = i / EE, e = i % EE;
    int dst = edges[(long long)b * 2 * EE + EE + e];
    atomicAdd(&g_cnt[b * 1026 + dst], 1);
}
__global__ void scan_kernel() {
    int b = threadIdx.x;
    if (b >= 8) return;
    int acc = 0;
    for (int i = 0; i < 1026; i++) {
        g_off[b * 1026 + i] = acc;
        g_cur[b * 1026 + i] = acc;
        if (i < 1025) acc += g_cnt[b * 1026 + i];
    }
}
__global__ void fill_kernel(const int* __restrict__ edges) {
    int i = blockIdx.x * blockDim.x + threadIdx.x;
    if (i >= BATCH * EE) return;
    int b = i / EE, e = i % EE;
    int dst = edges[(long long)b * 2 * EE + EE + e];
    int pos = atomicAdd(&g_cur[b * 1026 + dst], 1);
    g_elist[b * EE + pos] = e;
}

// ============================ fused GNN attention ============================
__device__ __forceinline__ unsigned fenc(float f) {
    unsigned u = __float_as_uint(f);
    return (u & 0x80000000u) ? ~u : (u | 0x80000000u);
}
__device__ __forceinline__ float fdec(unsigned e) {
    return (e & 0x80000000u) ? __uint_as_float(e ^ 0x80000000u) : __uint_as_float(~e);
}

__global__ __launch_bounds__(256) void gnn_edge_kernel(
    const float* __restrict__ q, const float* __restrict__ k, const float* __restrict__ v,
    float* __restrict__ h,
    const int* __restrict__ edges, const int* __restrict__ etyp,
    const float* __restrict__ ET)
{
    const int node = blockIdx.x;
    const int b = blockIdx.y;
    const int tid = threadIdx.x;
    const int lane = tid & 31;
    const int w = tid >> 5;
    __shared__ float qs[256];
    __shared__ unsigned smax[4];
    __shared__ float sden[4];
    __shared__ float sagg[256];
    const long long rowOff = ((long long)b * 1025 + node) * 256;
    qs[tid] = q[rowOff + tid];
    sagg[tid] = 0.f;
    if (tid < 4) { smax[tid] = 0u; sden[tid] = 0.f; }
    __syncthreads();
    const int off = g_off[b * 1026 + node];
    const int deg = g_off[b * 1026 + node + 1] - off;
    const int* el = g_elist + b * EE + off;
    const int* srcArr = edges + (long long)b * 2 * EE;

    float lmax[4] = { -1e30f, -1e30f, -1e30f, -1e30f };
    for (int ei = w; ei < deg; ei += 8) {
        int e = el[ei];
        int src = srcArr[e];
        int et = etyp[(long long)b * EE + e];
        const float* kr = k + ((long long)b * 1025 + src) * 256;
        const float* er = ET + et * 256;
        float hc[4] = {0.f, 0.f, 0.f, 0.f};
        #pragma unroll
        for (int i = 0; i < 8; i++) {
            int d = i * 32 + lane;
            hc[i >> 1] += qs[d] * (kr[d] + er[d]);
        }
        #pragma unroll
        for (int s = 16; s > 0; s >>= 1) {
            #pragma unroll
            for (int hh = 0; hh < 4; hh++) hc[hh] += __shfl_xor_sync(0xffffffffu, hc[hh], s);
        }
        #pragma unroll
        for (int hh = 0; hh < 4; hh++) lmax[hh] = fmaxf(lmax[hh], hc[hh] * 0.125f);
    }
    if (lane == 0 && deg > 0) {
        #pragma unroll
        for (int hh = 0; hh < 4; hh++) atomicMax(&smax[hh], fenc(lmax[hh]));
    }
    __syncthreads();
    float mx[4];
    #pragma unroll
    for (int hh = 0; hh < 4; hh++) mx[hh] = fdec(smax[hh]);

    float vacc[8] = {0.f, 0.f, 0.f, 0.f, 0.f, 0.f, 0.f, 0.f};
    float wsum[4] = {0.f, 0.f, 0.f, 0.f};
    for (int ei = w; ei < deg; ei += 8) {
        int e = el[ei];
        int src = srcArr[e];
        int et = etyp[(long long)b * EE + e];
        const float* kr = k + ((long long)b * 1025 + src) * 256;
        const float* er = ET + et * 256;
        float hc[4] = {0.f, 0.f, 0.f, 0.f};
        #pragma unroll
        for (int i = 0; i < 8; i++) {
            int d = i * 32 + lane;
            hc[i >> 1] += qs[d] * (kr[d] + er[d]);
        }
        #pragma unroll
        for (int s = 16; s > 0; s >>= 1) {
            #pragma unroll
            for (int hh = 0; hh < 4; hh++) hc[hh] += __shfl_xor_sync(0xffffffffu, hc[hh], s);
        }
        float ex[4];
        #pragma unroll
        for (int hh = 0; hh < 4; hh++) ex[hh] = expf(hc[hh] * 0.125f - mx[hh]);
        const float* vr = v + ((long long)b * 1025 + src) * 256;
        #pragma unroll
        for (int i = 0; i < 8; i++) {
            int d = i * 32 + lane;
            vacc[i] += ex[i >> 1] * vr[d];
        }
        if (lane == 0) {
            #pragma unroll
            for (int hh = 0; hh < 4; hh++) wsum[hh] += ex[hh];
        }
    }
    if (lane == 0 && deg > 0) {
        #pragma unroll
        for (int hh = 0; hh < 4; hh++) atomicAdd(&sden[hh], wsum[hh]);
    }
    #pragma unroll
    for (int i = 0; i < 8; i++) atomicAdd(&sagg[i * 32 + lane], vacc[i]);
    __syncthreads();
    float den = sden[tid >> 6] + 1e-9f;
    float val = h[rowOff + tid] + sagg[tid] / den;
    h[rowOff + tid] = fmaxf(val, 0.f);
}

// ============================ final classifier ============================
__global__ void out_kernel(float* __restrict__ out) {
    int c = blockIdx.x, b = blockIdx.y, t = threadIdx.x;
    __shared__ float red[256];
    const float* ctx = g_h + (long long)b * 1025 * 256;
    const float* lab = g_h + ((long long)b * 1025 + 1 + c) * 256;
    const float* txt = g_hin + (long long)b * 1025 * 768;
    float s = 0.f;
    for (int kx = t; kx < 1280; kx += 256) {
        float x;
        if (kx < 256) x = ctx[kx];
        else if (kx < 512) x = lab[kx - 256];
        else x = txt[kx - 512];
        s += x * g_Wc[kx * 50 + c];
    }
    red[t] = s;
    __syncthreads();
    for (int st = 128; st > 0; st >>= 1) { if (t < st) red[t] += red[t + st]; __syncthreads(); }
    if (t == 0) out[b * 50 + c] = red[0] + g_bc[c];
}

// ============================ host ============================
static void launch_gtc(const float* A, long long sA,
                       const float* gtab, const int* gidx, long long sG,
                       const __nv_bfloat16* BH, const __nv_bfloat16* BL,
                       float* C, long long sC, int Mr, int Nc, int Kd,
                       const float* bias, const float* rowScale, long long sRS,
                       const float* addTab, const int* aidx, long long sAI, int relu) {
    dim3 grid(Nc / 128, (Mr + 127) / 128, BATCH);
    gemm_mma<<<grid, 256>>>(A, sA, gtab, gidx, sG, BH, BL, C, sC, Mr, Nc, Kd,
                            bias, rowScale, sRS, addTab, aidx, sAI, relu);
}

extern "C" void kernel_launch(void* const* d_in, const int* in_sizes, int n_in,
                              void* d_out, int out_size) {
    (void)in_sizes; (void)n_in; (void)out_size;
    const int*   sentence        = (const int*)d_in[0];
    const float* mask            = (const float*)d_in[1];
    const int*   nodes           = (const int*)d_in[2];
    const float* node_mask       = (const float*)d_in[3];
    const int*   node_types      = (const int*)d_in[4];
    const int*   edges           = (const int*)d_in[5];
    const int*   edge_types      = (const int*)d_in[6];
    const float* word_embed      = (const float*)d_in[7];
    const float* entity_table    = (const float*)d_in[8];
    const float* type_table      = (const float*)d_in[9];
    const float* mlp_w1          = (const float*)d_in[10];
    const float* mlp_b1          = (const float*)d_in[11];
    const float* mlp_w2          = (const float*)d_in[12];
    const float* mlp_b2          = (const float*)d_in[13];
    const float* ntw_w           = (const float*)d_in[14];
    const float* proj_w          = (const float*)d_in[15];
    const float* proj_b          = (const float*)d_in[16];
    const float* type_proj_w     = (const float*)d_in[17];
    const float* edge_type_table = (const float*)d_in[18];
    const float* gnn_wq          = (const float*)d_in[19];
    const float* gnn_wk          = (const float*)d_in[20];
    const float* gnn_wv          = (const float*)d_in[21];
    const float* gnn_we          = (const float*)d_in[22];
    const float* cls_w           = (const float*)d_in[23];
    const float* cls_b           = (const float*)d_in[24];
    const float* cls2_w          = (const float*)d_in[25];
    const float* cls2_b          = (const float*)d_in[26];
    float* out = (float*)d_out;

    float *pH1, *pS, *pPool, *pHin, *pH, *pQ, *pK, *pV, *pTpv, *pET, *pWc, *pMsum;
    __nv_bfloat16 *pWH, *pWL;
    cudaGetSymbolAddress((void**)&pH1, g_H1);
    cudaGetSymbolAddress((void**)&pS, g_S);
    cudaGetSymbolAddress((void**)&pPool, g_pooled);
    cudaGetSymbolAddress((void**)&pHin, g_hin);
    cudaGetSymbolAddress((void**)&pH, g_h);
    cudaGetSymbolAddress((void**)&pQ, g_q);
    cudaGetSymbolAddress((void**)&pK, g_k);
    cudaGetSymbolAddress((void**)&pV, g_v);
    cudaGetSymbolAddress((void**)&pTpv, g_tpv);
    cudaGetSymbolAddress((void**)&pET, g_ET);
    cudaGetSymbolAddress((void**)&pWc, g_Wc);
    cudaGetSymbolAddress((void**)&pMsum, g_msum);
    cudaGetSymbolAddress((void**)&pWH, g_WH);
    cudaGetSymbolAddress((void**)&pWL, g_WL);

    // text vector
    text_kernel<<<8, 256>>>(sentence, mask, word_embed);
    // precomputes
    smallmm<<<(100 * 256 + 255) / 256, 256>>>(type_table, type_proj_w, pTpv, 100, 256, 50, 0);
    smallmm<<<(50 * 256 + 255) / 256, 256>>>(edge_type_table, gnn_we, pET, 50, 256, 50, 0);
    smallmm<<<(50 * 256 + 255) / 256, 256>>>(edge_type_table, gnn_we + 50 * 256, pET + 50 * 256, 50, 256, 50, 0);
    smallmm<<<(1280 * 50 + 255) / 256, 256>>>(cls_w, cls2_w, pWc, 1280, 50, 768, 1);
    bc_kernel<<<1, 64>>>(cls_b, cls2_w, cls2_b);
    msum_kernel<<<8, 1024>>>(node_mask);
    // weight transpose + bf16 split
    prep_w<<<(768 * 1024 + 255) / 256, 256>>>(mlp_w1, pWH + OFF_W1, pWL + OFF_W1, 768, 1024);
    prep_w<<<(1024 * 768 + 255) / 256, 256>>>(mlp_w2, pWH + OFF_W2, pWL + OFF_W2, 1024, 768);
    prep_w<<<(768 * 768 + 255) / 256, 256>>>(ntw_w, pWH + OFF_NTW, pWL + OFF_NTW, 768, 768);
    prep_w<<<(768 * 256 + 255) / 256, 256>>>(proj_w, pWH + OFF_PROJ, pWL + OFF_PROJ, 768, 256);
    for (int l = 0; l < 2; l++) {
        prep_w<<<(65536 + 255) / 256, 256>>>(gnn_wq + l * 65536, pWH + OFF_QKV + (l * 3 + 0) * 65536,
                                             pWL + OFF_QKV + (l * 3 + 0) * 65536, 256, 256);
        prep_w<<<(65536 + 255) / 256, 256>>>(gnn_wk + l * 65536, pWH + OFF_QKV + (l * 3 + 1) * 65536,
                                             pWL + OFF_QKV + (l * 3 + 1) * 65536, 256, 256);
        prep_w<<<(65536 + 255) / 256, 256>>>(gnn_wv + l * 65536, pWH + OFF_QKV + (l * 3 + 2) * 65536,
                                             pWL + OFF_QKV + (l * 3 + 2) * 65536, 256, 256);
    }
    // kg-half pooling
    poolkg_kernel<<<dim3(512, 8), 256>>>(nodes, node_mask, entity_table);
    // MLP1: relu(E[idx] @ W1 + b1) -> H1
    launch_gtc(nullptr, 0, entity_table, nodes + 4096, 8192,
               pWH + OFF_W1, pWL + OFF_W1, pH1, 4096LL * 1024, 4096, 1024, 768,
               mlp_b1, nullptr, 0, nullptr, nullptr, 0, 1);
    // masked sum over M -> S
    reduceS_kernel<<<dim3(512, 8), 256>>>(node_mask);
    // MLP2: S @ W2 + b2*msum
    launch_gtc(pS, 512LL * 1024, nullptr, nullptr, 0,
               pWH + OFF_W2, pWL + OFF_W2, pPool + 512 * 768, 1024LL * 768, 512, 768, 1024,
               mlp_b2, pMsum + 512, 1024, nullptr, nullptr, 0, 0);
    // ntw
    launch_gtc(pPool, 1024LL * 768, nullptr, nullptr, 0,
               pWH + OFF_NTW, pWL + OFF_NTW, pHin + 768, 1025LL * 768, 1024, 768, 768,
               nullptr, nullptr, 0, nullptr, nullptr, 0, 0);
    // proj (+ node-type embeds)
    launch_gtc(pHin, 1025LL * 768, nullptr, nullptr, 0,
               pWH + OFF_PROJ, pWL + OFF_PROJ, pH, 1025LL * 256, 1025, 256, 768,
               proj_b, nullptr, 0, pTpv, node_types, 1025, 0);
    // CSR
    zero_cnt<<<(8 * 1026 + 255) / 256, 256>>>();
    count_kernel<<<(BATCH * EE) / 256, 256>>>(edges);
    scan_kernel<<<1, 8>>>();
    fill_kernel<<<(BATCH * EE) / 256, 256>>>(edges);
    // GNN layers
    for (int l = 0; l < 2; l++) {
        launch_gtc(pH, 1025LL * 256, nullptr, nullptr, 0,
                   pWH + OFF_QKV + (l * 3 + 0) * 65536, pWL + OFF_QKV + (l * 3 + 0) * 65536,
                   pQ, 1025LL * 256, 1025, 256, 256, nullptr, nullptr, 0, nullptr, nullptr, 0, 0);
        launch_gtc(pH, 1025LL * 256, nullptr, nullptr, 0,
                   pWH + OFF_QKV + (l * 3 + 1) * 65536, pWL + OFF_QKV + (l * 3 + 1) * 65536,
                   pK, 1025LL * 256, 1025, 256, 256, nullptr, nullptr, 0, nullptr, nullptr, 0, 0);
        launch_gtc(pH, 1025LL * 256, nullptr, nullptr, 0,
                   pWH + OFF_QKV + (l * 3 + 2) * 65536, pWL + OFF_QKV + (l * 3 + 2) * 65536,
                   pV, 1025LL * 256, 1025, 256, 256, nullptr, nullptr, 0, nullptr, nullptr, 0, 0);
        gnn_edge_kernel<<<dim3(1025, 8), 256>>>(pQ, pK, pV, pH, edges, edge_types,
                                                pET + l * 50 * 256);
    }
    out_kernel<<<dim3(50, 8), 256>>>(out);
}